// round 11
// baseline (speedup 1.0000x reference)
#include <cuda_runtime.h>
#include <cuda_bf16.h>

// GCN_8632884265212 — 3-layer GCN on GB300.
// out = nd ∘ (A · (ns ∘ (X W))) + b  per layer (GEMM-first reorder).
// CSR-by-dst aggregation (no float atomics); Y (25.6 MB) stays L2-resident.

#define N_NODES 50000
#define DIM     128
#define DOUT    64
#define E_MAX   800000
#define SCAN_B  1024
#define N_TILES ((N_NODES + SCAN_B - 1) / SCAN_B)   // 49

// ---------------- scratch (static __device__ globals; no allocation) --------
__device__ float g_y[N_NODES * DIM];     // post-GEMM, ns-scaled
__device__ float g_h[N_NODES * DIM];     // layer output (intermediate)
__device__ float g_ns[N_NODES];
__device__ float g_nd[N_NODES];
__device__ int   g_outdeg[N_NODES];
__device__ int   g_indeg[N_NODES];
__device__ int   g_fill[N_NODES];        // seeded with rowptr; atomic cursor
__device__ int   g_rowptr[N_NODES + 1];
__device__ int   g_col[E_MAX];
__device__ int   g_blocksum[N_TILES];

// ---------------- graph build ----------------------------------------------
__global__ void zero_kernel() {
    int i = blockIdx.x * blockDim.x + threadIdx.x;
    if (i < N_NODES) {
        g_outdeg[i] = 0;
        g_indeg[i]  = 0;
    }
}

__global__ void count_kernel(const int* __restrict__ src,
                             const int* __restrict__ dst, int E) {
    int e = blockIdx.x * blockDim.x + threadIdx.x;
    if (e < E) {
        atomicAdd(&g_outdeg[src[e]], 1);
        atomicAdd(&g_indeg[dst[e]], 1);
    }
}

__global__ void norm_kernel() {
    int i = blockIdx.x * blockDim.x + threadIdx.x;
    if (i < N_NODES) {
        g_ns[i] = rsqrtf(fmaxf((float)g_outdeg[i], 1.0f));
        g_nd[i] = rsqrtf(fmaxf((float)g_indeg[i], 1.0f));
    }
}

// decoupled 3-phase exclusive scan of g_indeg -> g_rowptr
__global__ void scan_tiles_kernel() {           // N_TILES blocks x 1024
    __shared__ int sh[SCAN_B];
    int t = threadIdx.x;
    int idx = blockIdx.x * SCAN_B + t;
    int v = (idx < N_NODES) ? g_indeg[idx] : 0;
    sh[t] = v;
    __syncthreads();
    #pragma unroll
    for (int off = 1; off < SCAN_B; off <<= 1) {
        int x = (t >= off) ? sh[t - off] : 0;
        __syncthreads();
        sh[t] += x;
        __syncthreads();
    }
    if (idx < N_NODES) g_rowptr[idx] = sh[t] - v;   // tile-local exclusive
    if (t == SCAN_B - 1) g_blocksum[blockIdx.x] = sh[t];
}

__global__ void scan_sums_kernel() {            // 1 block, 64 threads
    __shared__ int sh[64];
    int t = threadIdx.x;
    int v = (t < N_TILES) ? g_blocksum[t] : 0;
    sh[t] = v;
    __syncthreads();
    #pragma unroll
    for (int off = 1; off < 64; off <<= 1) {
        int x = (t >= off) ? sh[t - off] : 0;
        __syncthreads();
        sh[t] += x;
        __syncthreads();
    }
    if (t < N_TILES) g_blocksum[t] = sh[t] - v; // exclusive
    if (t == 63) g_rowptr[N_NODES] = sh[63];    // total = E
}

__global__ void scan_add_kernel() {             // N_TILES blocks x 1024
    int idx = blockIdx.x * SCAN_B + threadIdx.x;
    if (idx < N_NODES) {
        int p = g_rowptr[idx] + g_blocksum[blockIdx.x];
        g_rowptr[idx] = p;
        g_fill[idx] = p;                        // seed fill cursor = rowptr
    }
}

__global__ void fill_kernel(const int* __restrict__ src,
                            const int* __restrict__ dst, int E) {
    int e = blockIdx.x * blockDim.x + threadIdx.x;
    if (e < E) {
        int p = atomicAdd(&g_fill[dst[e]], 1);  // absolute slot, single atomic
        g_col[p] = src[e];
    }
}

// ---------------- GEMM: g_y = ns ∘ (X[N,128] * W[128,NOUT]) -----------------
// BM=128, BK=32, 8x8 (or 4x8) register blocking; As stored k-major with +4 pad
// so every row is 16B-aligned for LDS.128 (row stride 132 floats = 33*16B).
// __align__(16) on the shared tiles makes the base alignment contractual.
template <int NOUT, bool FROM_H>
__global__ __launch_bounds__(256)
void gemm_scale_kernel(const float* __restrict__ Xin,
                       const float* __restrict__ W) {
    constexpr int BM = 128, BK = 32;
    constexpr int TN = 8;
    constexpr int CG = NOUT / TN;      // col groups: 16 (D=128) / 8 (D=64)
    constexpr int RG = 256 / CG;       // row groups: 16 / 32
    constexpr int TM = BM / RG;        // rows/thread: 8 / 4

    const float* __restrict__ X = FROM_H ? g_h : Xin;

    __shared__ __align__(16) float As[BK][BM + 4];  // +4 pad: rows 16B-aligned
    __shared__ __align__(16) float Ws[BK][NOUT];

    int tid = threadIdx.x;
    int block_row = blockIdx.x * BM;
    int tx = tid % CG;
    int ty = tid / CG;

    float acc[TM][TN];
    #pragma unroll
    for (int i = 0; i < TM; i++)
        #pragma unroll
        for (int j = 0; j < TN; j++) acc[i][j] = 0.0f;

    for (int k0 = 0; k0 < DIM; k0 += BK) {
        // A tile: 128 rows x 32 cols, coalesced row reads, transposed store
        #pragma unroll
        for (int i = tid; i < BM * BK; i += 256) {
            int r = i / BK, c = i % BK;
            int gr = block_row + r;
            As[c][r] = (gr < N_NODES) ? X[gr * DIM + k0 + c] : 0.0f;
        }
        // W tile: 32 x NOUT
        #pragma unroll
        for (int i = tid; i < BK * NOUT; i += 256) {
            int r = i / NOUT, c = i % NOUT;
            Ws[r][c] = W[(k0 + r) * NOUT + c];
        }
        __syncthreads();

        #pragma unroll
        for (int k = 0; k < BK; k++) {
            float a[TM];
            #pragma unroll
            for (int i = 0; i < TM; i += 4) {
                float4 a4 = *reinterpret_cast<const float4*>(&As[k][ty * TM + i]);
                a[i + 0] = a4.x; a[i + 1] = a4.y; a[i + 2] = a4.z; a[i + 3] = a4.w;
            }
            float w[TN];
            #pragma unroll
            for (int j = 0; j < TN; j += 4) {
                float4 w4 = *reinterpret_cast<const float4*>(&Ws[k][tx * TN + j]);
                w[j + 0] = w4.x; w[j + 1] = w4.y; w[j + 2] = w4.z; w[j + 3] = w4.w;
            }
            #pragma unroll
            for (int i = 0; i < TM; i++)
                #pragma unroll
                for (int j = 0; j < TN; j++)
                    acc[i][j] += a[i] * w[j];
        }
        __syncthreads();
    }

    #pragma unroll
    for (int i = 0; i < TM; i++) {
        int r = block_row + ty * TM + i;
        if (r < N_NODES) {
            float s = g_ns[r];
            #pragma unroll
            for (int j = 0; j < TN; j += 4) {
                float4 o;
                o.x = s * acc[i][j + 0];
                o.y = s * acc[i][j + 1];
                o.z = s * acc[i][j + 2];
                o.w = s * acc[i][j + 3];
                *reinterpret_cast<float4*>(&g_y[r * NOUT + tx * TN + j]) = o;
            }
        }
    }
}

// -------- aggregation: dest[n] = relu?(nd[n] * sum_{s in N(n)} g_y[s] + b) --
// Unroll-by-4 index prefetch to raise gather MLP (mean degree = 16).
template <int D, bool RELU, bool TO_H>
__global__ __launch_bounds__(256)
void agg_kernel(const float* __restrict__ bias, float* __restrict__ out_p) {
    constexpr int LPN = D / 4;                   // lanes per node (32 or 16)
    float* __restrict__ dest = TO_H ? g_h : out_p;

    int gt = blockIdx.x * blockDim.x + threadIdx.x;
    int node = gt / LPN;
    int lane = gt % LPN;
    if (node >= N_NODES) return;

    int beg = g_rowptr[node];
    int end = g_rowptr[node + 1];

    float ax = 0.f, ay = 0.f, az = 0.f, aw = 0.f;
    float bx = 0.f, by = 0.f, bz = 0.f, bw = 0.f;

    int e = beg;
    for (; e + 4 <= end; e += 4) {
        int s0 = g_col[e];
        int s1 = g_col[e + 1];
        int s2 = g_col[e + 2];
        int s3 = g_col[e + 3];
        float4 v0 = *reinterpret_cast<const float4*>(&g_y[s0 * D + lane * 4]);
        float4 v1 = *reinterpret_cast<const float4*>(&g_y[s1 * D + lane * 4]);
        float4 v2 = *reinterpret_cast<const float4*>(&g_y[s2 * D + lane * 4]);
        float4 v3 = *reinterpret_cast<const float4*>(&g_y[s3 * D + lane * 4]);
        ax += v0.x; ay += v0.y; az += v0.z; aw += v0.w;
        bx += v1.x; by += v1.y; bz += v1.z; bw += v1.w;
        ax += v2.x; ay += v2.y; az += v2.z; aw += v2.w;
        bx += v3.x; by += v3.y; bz += v3.z; bw += v3.w;
    }
    for (; e < end; e++) {
        int s0 = g_col[e];
        float4 v0 = *reinterpret_cast<const float4*>(&g_y[s0 * D + lane * 4]);
        ax += v0.x; ay += v0.y; az += v0.z; aw += v0.w;
    }
    ax += bx; ay += by; az += bz; aw += bw;

    float sc = g_nd[node];
    float4 b4 = *reinterpret_cast<const float4*>(&bias[lane * 4]);
    float4 o;
    o.x = ax * sc + b4.x;
    o.y = ay * sc + b4.y;
    o.z = az * sc + b4.z;
    o.w = aw * sc + b4.w;
    if (RELU) {
        o.x = fmaxf(o.x, 0.f);
        o.y = fmaxf(o.y, 0.f);
        o.z = fmaxf(o.z, 0.f);
        o.w = fmaxf(o.w, 0.f);
    }
    *reinterpret_cast<float4*>(&dest[node * D + lane * 4]) = o;
}

extern "C" void kernel_launch(void* const* d_in, const int* in_sizes, int n_in,
                              void* d_out, int out_size) {
    const float* features = (const float*)d_in[0];
    const float* W1 = (const float*)d_in[1];
    const float* b1 = (const float*)d_in[2];
    const float* W2 = (const float*)d_in[3];
    const float* b2 = (const float*)d_in[4];
    const float* W3 = (const float*)d_in[5];
    const float* b3 = (const float*)d_in[6];
    const int*   src = (const int*)d_in[7];
    const int*   dst = (const int*)d_in[8];
    float* out = (float*)d_out;
    int E = in_sizes[7];

    int nblk = (N_NODES + 255) / 256;
    int eblk = (E + 255) / 256;

    // graph build
    zero_kernel<<<nblk, 256>>>();
    count_kernel<<<eblk, 256>>>(src, dst, E);
    norm_kernel<<<nblk, 256>>>();
    scan_tiles_kernel<<<N_TILES, SCAN_B>>>();
    scan_sums_kernel<<<1, 64>>>();
    scan_add_kernel<<<N_TILES, SCAN_B>>>();
    fill_kernel<<<eblk, 256>>>(src, dst, E);

    int gemm_grid = (N_NODES + 127) / 128;
    int agg_grid_128 = (N_NODES * (DIM / 4) + 255) / 256;
    int agg_grid_64  = (N_NODES * (DOUT / 4) + 255) / 256;

    // layer 1: Y = ns ∘ (X W1); H = relu(nd ∘ (A Y) + b1)
    gemm_scale_kernel<DIM, false><<<gemm_grid, 256>>>(features, W1);
    agg_kernel<DIM, true, true><<<agg_grid_128, 256>>>(b1, nullptr);

    // layer 2
    gemm_scale_kernel<DIM, true><<<gemm_grid, 256>>>(nullptr, W2);
    agg_kernel<DIM, true, true><<<agg_grid_128, 256>>>(b2, nullptr);

    // layer 3 (64-wide aggregation, no relu) -> d_out
    gemm_scale_kernel<DOUT, true><<<gemm_grid, 256>>>(nullptr, W3);
    agg_kernel<DOUT, false, false><<<agg_grid_64, 256>>>(b3, out);
}

// round 16
// speedup vs baseline: 1.6488x; 1.6488x over previous
#include <cuda_runtime.h>
#include <cuda_bf16.h>
#include <cstdint>

// GCN_8632884265212 — 3-layer GCN on GB300.
// out = nd ∘ (A · (ns ∘ (X W))) + b  per layer (GEMM-first reorder).
// CSR-by-dst aggregation (no float atomics); Y (25.6 MB) stays L2-resident.
// GEMM now uses tf32 mma.sync.m16n8k8 tensor cores (fp32 accumulate).

#define N_NODES 50000
#define DIM     128
#define DOUT    64
#define E_MAX   800000
#define SCAN_B  1024
#define N_TILES ((N_NODES + SCAN_B - 1) / SCAN_B)   // 49

// ---------------- scratch (static __device__ globals; no allocation) --------
__device__ float g_y[N_NODES * DIM];     // post-GEMM, ns-scaled
__device__ float g_h[N_NODES * DIM];     // layer output (intermediate)
__device__ float g_ns[N_NODES];
__device__ float g_nd[N_NODES];
__device__ int   g_outdeg[N_NODES];
__device__ int   g_indeg[N_NODES];
__device__ int   g_fill[N_NODES];        // seeded with rowptr; atomic cursor
__device__ int   g_rowptr[N_NODES + 1];
__device__ int   g_col[E_MAX];
__device__ int   g_blocksum[N_TILES];

// ---------------- graph build ----------------------------------------------
__global__ void zero_kernel() {
    int i = blockIdx.x * blockDim.x + threadIdx.x;
    if (i < N_NODES) {
        g_outdeg[i] = 0;
        g_indeg[i]  = 0;
    }
}

__global__ void count_kernel(const int* __restrict__ src,
                             const int* __restrict__ dst, int E) {
    int e = blockIdx.x * blockDim.x + threadIdx.x;
    if (e < E) {
        atomicAdd(&g_outdeg[src[e]], 1);
        atomicAdd(&g_indeg[dst[e]], 1);
    }
}

__global__ void norm_kernel() {
    int i = blockIdx.x * blockDim.x + threadIdx.x;
    if (i < N_NODES) {
        g_ns[i] = rsqrtf(fmaxf((float)g_outdeg[i], 1.0f));
        g_nd[i] = rsqrtf(fmaxf((float)g_indeg[i], 1.0f));
    }
}

// decoupled 3-phase exclusive scan of g_indeg -> g_rowptr
__global__ void scan_tiles_kernel() {           // N_TILES blocks x 1024
    __shared__ int sh[SCAN_B];
    int t = threadIdx.x;
    int idx = blockIdx.x * SCAN_B + t;
    int v = (idx < N_NODES) ? g_indeg[idx] : 0;
    sh[t] = v;
    __syncthreads();
    #pragma unroll
    for (int off = 1; off < SCAN_B; off <<= 1) {
        int x = (t >= off) ? sh[t - off] : 0;
        __syncthreads();
        sh[t] += x;
        __syncthreads();
    }
    if (idx < N_NODES) g_rowptr[idx] = sh[t] - v;   // tile-local exclusive
    if (t == SCAN_B - 1) g_blocksum[blockIdx.x] = sh[t];
}

__global__ void scan_sums_kernel() {            // 1 block, 64 threads
    __shared__ int sh[64];
    int t = threadIdx.x;
    int v = (t < N_TILES) ? g_blocksum[t] : 0;
    sh[t] = v;
    __syncthreads();
    #pragma unroll
    for (int off = 1; off < 64; off <<= 1) {
        int x = (t >= off) ? sh[t - off] : 0;
        __syncthreads();
        sh[t] += x;
        __syncthreads();
    }
    if (t < N_TILES) g_blocksum[t] = sh[t] - v; // exclusive
    if (t == 63) g_rowptr[N_NODES] = sh[63];    // total = E
}

__global__ void scan_add_kernel() {             // N_TILES blocks x 1024
    int idx = blockIdx.x * SCAN_B + threadIdx.x;
    if (idx < N_NODES) {
        int p = g_rowptr[idx] + g_blocksum[blockIdx.x];
        g_rowptr[idx] = p;
        g_fill[idx] = p;                        // seed fill cursor = rowptr
    }
}

__global__ void fill_kernel(const int* __restrict__ src,
                            const int* __restrict__ dst, int E) {
    int e = blockIdx.x * blockDim.x + threadIdx.x;
    if (e < E) {
        int p = atomicAdd(&g_fill[dst[e]], 1);  // absolute slot, single atomic
        g_col[p] = src[e];
    }
}

// ---------------- tf32 mma helpers ------------------------------------------
__device__ __forceinline__ uint32_t f2tf32(float f) {
    uint32_t r;
    asm("cvt.rna.tf32.f32 %0, %1;" : "=r"(r) : "f"(f));
    return r;
}

__device__ __forceinline__ void mma_tf32(float* d, const uint32_t* a,
                                         uint32_t b0, uint32_t b1) {
    asm volatile(
        "mma.sync.aligned.m16n8k8.row.col.f32.tf32.tf32.f32 "
        "{%0,%1,%2,%3}, {%4,%5,%6,%7}, {%8,%9}, {%0,%1,%2,%3};"
        : "+f"(d[0]), "+f"(d[1]), "+f"(d[2]), "+f"(d[3])
        : "r"(a[0]), "r"(a[1]), "r"(a[2]), "r"(a[3]), "r"(b0), "r"(b1));
}

// ---------------- GEMM: g_y = ns ∘ (X[N,128] * W[128,NOUT]) -----------------
// tf32 tensor cores. Block 128 x NOUT, 8 warps as 4(M) x 2(N); warp tile
// 32 x (NOUT/2). A tile m-major [BM][BK+4] (a-frag reads: 32 distinct banks),
// W tile [BK][NOUT+4].
template <int NOUT, bool FROM_H>
__global__ __launch_bounds__(256)
void gemm_tf32_kernel(const float* __restrict__ Xin,
                      const float* __restrict__ W) {
    constexpr int BM = 128, BK = 32;
    constexpr int WTN = NOUT / 2;      // 64 (D=128) / 32 (D=64)
    constexpr int NT  = WTN / 8;       // 8 / 4 mma tiles in N per warp

    const float* __restrict__ X = FROM_H ? g_h : Xin;

    __shared__ __align__(16) float As[BM][BK + 4];      // rows 144B (9*16B)
    __shared__ __align__(16) float Ws[BK][NOUT + 4];    // rows 528/272B

    int tid   = threadIdx.x;
    int lane  = tid % 32;
    int wid   = tid / 32;
    int warp_m = wid % 4;              // 0..3
    int warp_n = wid / 4;              // 0..1
    int grp = lane / 4;                // 0..7 (groupID)
    int tig = lane % 4;                // 0..3 (thread in group)
    int block_row = blockIdx.x * BM;

    float acc[2][NT][4];
    #pragma unroll
    for (int mt = 0; mt < 2; mt++)
        #pragma unroll
        for (int nt = 0; nt < NT; nt++)
            #pragma unroll
            for (int q = 0; q < 4; q++) acc[mt][nt][q] = 0.0f;

    for (int k0 = 0; k0 < DIM; k0 += BK) {
        // A tile: 128 x 32 floats via float4 (warp covers whole rows)
        #pragma unroll
        for (int i = tid; i < BM * (BK / 4); i += 256) {
            int r  = i / (BK / 4);
            int c4 = i % (BK / 4);
            int gr = block_row + r;
            float4 v = make_float4(0.f, 0.f, 0.f, 0.f);
            if (gr < N_NODES)
                v = *reinterpret_cast<const float4*>(&X[gr * DIM + k0 + c4 * 4]);
            *reinterpret_cast<float4*>(&As[r][c4 * 4]) = v;
        }
        // W tile: 32 x NOUT via float4
        #pragma unroll
        for (int i = tid; i < BK * (NOUT / 4); i += 256) {
            int r  = i / (NOUT / 4);
            int c4 = i % (NOUT / 4);
            float4 v = *reinterpret_cast<const float4*>(&W[(k0 + r) * NOUT + c4 * 4]);
            *reinterpret_cast<float4*>(&Ws[r][c4 * 4]) = v;
        }
        __syncthreads();

        #pragma unroll
        for (int kc = 0; kc < BK; kc += 8) {
            uint32_t afr[2][4];
            #pragma unroll
            for (int mt = 0; mt < 2; mt++) {
                int ar = warp_m * 32 + mt * 16 + grp;
                afr[mt][0] = f2tf32(As[ar    ][kc + tig    ]);
                afr[mt][1] = f2tf32(As[ar + 8][kc + tig    ]);
                afr[mt][2] = f2tf32(As[ar    ][kc + tig + 4]);
                afr[mt][3] = f2tf32(As[ar + 8][kc + tig + 4]);
            }
            #pragma unroll
            for (int nt = 0; nt < NT; nt++) {
                int bc = warp_n * WTN + nt * 8 + grp;
                uint32_t b0 = f2tf32(Ws[kc + tig    ][bc]);
                uint32_t b1 = f2tf32(Ws[kc + tig + 4][bc]);
                mma_tf32(acc[0][nt], afr[0], b0, b1);
                mma_tf32(acc[1][nt], afr[1], b0, b1);
            }
        }
        __syncthreads();
    }

    // epilogue: scale by ns, store (d0,d1)->row grp, (d2,d3)->row grp+8
    #pragma unroll
    for (int mt = 0; mt < 2; mt++) {
        int r0 = block_row + warp_m * 32 + mt * 16 + grp;
        int r1 = r0 + 8;
        float s0 = (r0 < N_NODES) ? g_ns[r0] : 0.0f;
        float s1 = (r1 < N_NODES) ? g_ns[r1] : 0.0f;
        #pragma unroll
        for (int nt = 0; nt < NT; nt++) {
            int c = warp_n * WTN + nt * 8 + tig * 2;
            if (r0 < N_NODES) {
                float2 o = make_float2(s0 * acc[mt][nt][0], s0 * acc[mt][nt][1]);
                *reinterpret_cast<float2*>(&g_y[r0 * NOUT + c]) = o;
            }
            if (r1 < N_NODES) {
                float2 o = make_float2(s1 * acc[mt][nt][2], s1 * acc[mt][nt][3]);
                *reinterpret_cast<float2*>(&g_y[r1 * NOUT + c]) = o;
            }
        }
    }
}

// -------- aggregation: dest[n] = relu?(nd[n] * sum_{s in N(n)} g_y[s] + b) --
// Unroll-by-4 index prefetch to raise gather MLP (mean degree = 16).
template <int D, bool RELU, bool TO_H>
__global__ __launch_bounds__(256)
void agg_kernel(const float* __restrict__ bias, float* __restrict__ out_p) {
    constexpr int LPN = D / 4;                   // lanes per node (32 or 16)
    float* __restrict__ dest = TO_H ? g_h : out_p;

    int gt = blockIdx.x * blockDim.x + threadIdx.x;
    int node = gt / LPN;
    int lane = gt % LPN;
    if (node >= N_NODES) return;

    int beg = g_rowptr[node];
    int end = g_rowptr[node + 1];

    float ax = 0.f, ay = 0.f, az = 0.f, aw = 0.f;
    float bx = 0.f, by = 0.f, bz = 0.f, bw = 0.f;

    int e = beg;
    for (; e + 4 <= end; e += 4) {
        int s0 = g_col[e];
        int s1 = g_col[e + 1];
        int s2 = g_col[e + 2];
        int s3 = g_col[e + 3];
        float4 v0 = *reinterpret_cast<const float4*>(&g_y[s0 * D + lane * 4]);
        float4 v1 = *reinterpret_cast<const float4*>(&g_y[s1 * D + lane * 4]);
        float4 v2 = *reinterpret_cast<const float4*>(&g_y[s2 * D + lane * 4]);
        float4 v3 = *reinterpret_cast<const float4*>(&g_y[s3 * D + lane * 4]);
        ax += v0.x; ay += v0.y; az += v0.z; aw += v0.w;
        bx += v1.x; by += v1.y; bz += v1.z; bw += v1.w;
        ax += v2.x; ay += v2.y; az += v2.z; aw += v2.w;
        bx += v3.x; by += v3.y; bz += v3.z; bw += v3.w;
    }
    for (; e < end; e++) {
        int s0 = g_col[e];
        float4 v0 = *reinterpret_cast<const float4*>(&g_y[s0 * D + lane * 4]);
        ax += v0.x; ay += v0.y; az += v0.z; aw += v0.w;
    }
    ax += bx; ay += by; az += bz; aw += bw;

    float sc = g_nd[node];
    float4 b4 = *reinterpret_cast<const float4*>(&bias[lane * 4]);
    float4 o;
    o.x = ax * sc + b4.x;
    o.y = ay * sc + b4.y;
    o.z = az * sc + b4.z;
    o.w = aw * sc + b4.w;
    if (RELU) {
        o.x = fmaxf(o.x, 0.f);
        o.y = fmaxf(o.y, 0.f);
        o.z = fmaxf(o.z, 0.f);
        o.w = fmaxf(o.w, 0.f);
    }
    *reinterpret_cast<float4*>(&dest[node * D + lane * 4]) = o;
}

extern "C" void kernel_launch(void* const* d_in, const int* in_sizes, int n_in,
                              void* d_out, int out_size) {
    const float* features = (const float*)d_in[0];
    const float* W1 = (const float*)d_in[1];
    const float* b1 = (const float*)d_in[2];
    const float* W2 = (const float*)d_in[3];
    const float* b2 = (const float*)d_in[4];
    const float* W3 = (const float*)d_in[5];
    const float* b3 = (const float*)d_in[6];
    const int*   src = (const int*)d_in[7];
    const int*   dst = (const int*)d_in[8];
    float* out = (float*)d_out;
    int E = in_sizes[7];

    int nblk = (N_NODES + 255) / 256;
    int eblk = (E + 255) / 256;
    int gemm_grid = (N_NODES + 127) / 128;
    int agg_grid_128 = (N_NODES * (DIM / 4) + 255) / 256;
    int agg_grid_64  = (N_NODES * (DOUT / 4) + 255) / 256;

    // launch order: gemm1 at index 3 so ncu (-s 5, ~2 harness launches) lands
    // on it. gemm1 needs only g_ns; CSR build completes before agg1.
    zero_kernel<<<nblk, 256>>>();                                    // 0
    count_kernel<<<eblk, 256>>>(src, dst, E);                        // 1
    norm_kernel<<<nblk, 256>>>();                                    // 2
    gemm_tf32_kernel<DIM, false><<<gemm_grid, 256>>>(features, W1);  // 3
    scan_tiles_kernel<<<N_TILES, SCAN_B>>>();                        // 4
    scan_sums_kernel<<<1, 64>>>();                                   // 5
    scan_add_kernel<<<N_TILES, SCAN_B>>>();                          // 6
    fill_kernel<<<eblk, 256>>>(src, dst, E);                         // 7

    agg_kernel<DIM, true, true><<<agg_grid_128, 256>>>(b1, nullptr); // 8
    gemm_tf32_kernel<DIM, true><<<gemm_grid, 256>>>(nullptr, W2);    // 9
    agg_kernel<DIM, true, true><<<agg_grid_128, 256>>>(b2, nullptr); // 10
    gemm_tf32_kernel<DOUT, true><<<gemm_grid, 256>>>(nullptr, W3);   // 11
    agg_kernel<DOUT, false, false><<<agg_grid_64, 256>>>(b3, out);   // 12
}